// round 1
// baseline (speedup 1.0000x reference)
#include <cuda_runtime.h>
#include <cuda_bf16.h>
#include <mma.h>
#include <type_traits>

using namespace nvcuda;

namespace cfg {
constexpr int B = 8, T = 2048, C = 512;
constexpr int BT = B * T;                 // 16384
constexpr long long NTT = (long long)B * T * T;  // 33,554,432
}

// ---------------- scratch (static device arrays; no allocation) ----------------
__device__ __nv_bfloat16 g_xl16[cfg::BT * cfg::C];
__device__ __nv_bfloat16 g_xr16[cfg::BT * cfg::C];
__device__ __nv_bfloat16 g_w16[6 * cfg::C * cfg::C];   // lp1,rp1,lp2,rp2,lp3,rp3 (bf16)
__device__ __nv_bfloat16 g_h16[cfg::BT * cfg::C];
__device__ __nv_bfloat16 g_Ql[cfg::BT * cfg::C];
__device__ __nv_bfloat16 g_Qr[cfg::BT * cfg::C];
__device__ __nv_bfloat16 g_Vl[cfg::BT * cfg::C];
__device__ __nv_bfloat16 g_Vr[cfg::BT * cfg::C];
__device__ __nv_bfloat16 g_S [cfg::B * cfg::T * cfg::T];
__device__ __nv_bfloat16 g_P1[cfg::B * cfg::T * cfg::T];
__device__ __nv_bfloat16 g_P2[cfg::B * cfg::T * cfg::T];
__device__ __nv_bfloat16 g_F1[cfg::BT * cfg::C];
__device__ __nv_bfloat16 g_F2[cfg::BT * cfg::C];

// ---------------- small kernels ----------------
__global__ void k_f2bf(const float* __restrict__ in, __nv_bfloat16* __restrict__ out, int n4) {
    int i = blockIdx.x * blockDim.x + threadIdx.x;
    if (i < n4) {
        float4 f = reinterpret_cast<const float4*>(in)[i];
        __nv_bfloat162* o = reinterpret_cast<__nv_bfloat162*>(out);
        o[2 * i]     = __floats2bfloat162_rn(f.x, f.y);
        o[2 * i + 1] = __floats2bfloat162_rn(f.z, f.w);
    }
}

// depthwise conv k=3 pad=1 over T, per channel; h (B,T,C) bf16 -> out bf16
__global__ void k_dwconv(const __nv_bfloat16* __restrict__ h,
                         const float* __restrict__ w2,   // (C,3)
                         const float* __restrict__ b2,   // (C,)
                         __nv_bfloat16* __restrict__ out) {
    int i = blockIdx.x * blockDim.x + threadIdx.x;
    if (i >= cfg::BT * cfg::C) return;
    int c = i % cfg::C;
    int t = (i / cfg::C) % cfg::T;
    float v = __bfloat162float(h[i]) * w2[c * 3 + 1] + b2[c];
    if (t > 0)          v += __bfloat162float(h[i - cfg::C]) * w2[c * 3 + 0];
    if (t < cfg::T - 1) v += __bfloat162float(h[i + cfg::C]) * w2[c * 3 + 2];
    out[i] = __float2bfloat16(v);
}

// softmax over last axis: one block per row of length T
__global__ void k_softmax_row(const __nv_bfloat16* __restrict__ S, __nv_bfloat16* __restrict__ P) {
    const int row = blockIdx.x;
    const __nv_bfloat16* s = S + (size_t)row * cfg::T;
    __nv_bfloat16* p = P + (size_t)row * cfg::T;
    const int tid = threadIdx.x;  // 256 threads, 8 elems each
    float v[8];
    float m = -1e30f;
#pragma unroll
    for (int j = 0; j < 8; j++) { v[j] = __bfloat162float(s[tid + j * 256]); m = fmaxf(m, v[j]); }
    __shared__ float red[256];
    red[tid] = m; __syncthreads();
    for (int o = 128; o > 0; o >>= 1) { if (tid < o) red[tid] = fmaxf(red[tid], red[tid + o]); __syncthreads(); }
    m = red[0]; __syncthreads();
    float sum = 0.f;
#pragma unroll
    for (int j = 0; j < 8; j++) { v[j] = __expf(v[j] - m); sum += v[j]; }
    red[tid] = sum; __syncthreads();
    for (int o = 128; o > 0; o >>= 1) { if (tid < o) red[tid] += red[tid + o]; __syncthreads(); }
    float inv = 1.f / red[0];
#pragma unroll
    for (int j = 0; j < 8; j++) p[tid + j * 256] = __float2bfloat16(v[j] * inv);
}

// softmax over axis 1 (t) of S[b,t,s]: block = (32 s-columns) x (8 t-lanes)
__global__ void k_softmax_col(const __nv_bfloat16* __restrict__ S, __nv_bfloat16* __restrict__ P) {
    const int b = blockIdx.y;
    const int s = blockIdx.x * 32 + threadIdx.x;
    const int ty = threadIdx.y;  // 0..7
    const __nv_bfloat16* base = S + (size_t)b * cfg::T * cfg::T + s;
    __nv_bfloat16* pb = P + (size_t)b * cfg::T * cfg::T + s;
    float m = -1e30f;
    for (int t = ty; t < cfg::T; t += 8)
        m = fmaxf(m, __bfloat162float(base[(size_t)t * cfg::T]));
    __shared__ float red[8][32];
    red[ty][threadIdx.x] = m; __syncthreads();
    if (ty == 0) {
        float mm = red[0][threadIdx.x];
#pragma unroll
        for (int i = 1; i < 8; i++) mm = fmaxf(mm, red[i][threadIdx.x]);
        red[0][threadIdx.x] = mm;
    }
    __syncthreads();
    m = red[0][threadIdx.x];
    __syncthreads();
    float sum = 0.f;
    for (int t = ty; t < cfg::T; t += 8)
        sum += __expf(__bfloat162float(base[(size_t)t * cfg::T]) - m);
    red[ty][threadIdx.x] = sum; __syncthreads();
    if (ty == 0) {
        float ss = 0.f;
#pragma unroll
        for (int i = 0; i < 8; i++) ss += red[i][threadIdx.x];
        red[0][threadIdx.x] = ss;
    }
    __syncthreads();
    float inv = 1.f / red[0][threadIdx.x];
    for (int t = ty; t < cfg::T; t += 8)
        pb[(size_t)t * cfg::T] =
            __float2bfloat16(__expf(__bfloat162float(base[(size_t)t * cfg::T]) - m) * inv);
}

// ---------------- generic bf16 wmma GEMM ----------------
// C[m,n] = sum_k A[m,k]*B[k,n]
//  A_COL  : 0 -> A stored row-major (m,k) with lda;  1 -> A stored (k,m) with lda (i.e. op(A)=A_gmem^T)
//  B_NMAJ : 1 -> B stored (n,k) with ldb (B = W[n,k], i.e. multiply by W^T); 0 -> B stored (k,n) with ldb
//  MODE   : 0 -> out bf16 = acc*scale (+bias[n]);  1 -> out f32 = acc*scale + bias[n] + res[m*ldc+n]
template <int A_COL, int B_NMAJ, int MODE>
__global__ __launch_bounds__(256)
void k_gemm(const __nv_bfloat16* __restrict__ A,
            const __nv_bfloat16* __restrict__ Bm,
            void* __restrict__ Cout,
            const float* __restrict__ bias,
            const float* __restrict__ res,
            int M, int N, int K,
            int lda, int ldb, int ldc,
            long long sA, long long sB, long long sC,
            float scale) {
    constexpr int BM = 128, BN = 128, BK = 32;
    constexpr int LDAS  = A_COL ? 136 : 40;   // elems (pad for banks; 16B-aligned rows, 32B frag align)
    constexpr int AROWS = A_COL ? BK : BM;
    constexpr int LDBS  = B_NMAJ ? 40 : 136;
    constexpr int BROWS = B_NMAJ ? BN : BK;

    __shared__ __align__(16) __nv_bfloat16 As[2][AROWS * LDAS];
    __shared__ __align__(16) __nv_bfloat16 Bs[2][BROWS * LDBS];

    const int tid = threadIdx.x;
    const int bz = blockIdx.z;
    const int m0 = blockIdx.y * BM;
    const int n0 = blockIdx.x * BN;
    A  += (size_t)bz * sA;
    Bm += (size_t)bz * sB;

    const int w = tid >> 5, lane = tid & 31;
    const int wm = w >> 2, wn = w & 3;  // warp grid 2 (M) x 4 (N), warp tile 64x32

    wmma::fragment<wmma::accumulator, 16, 16, 16, float> acc[4][2];
#pragma unroll
    for (int i = 0; i < 4; i++)
#pragma unroll
        for (int j = 0; j < 2; j++) wmma::fill_fragment(acc[i][j], 0.0f);

    const int nk = K / BK;
    uint4 ra[2], rb[2];

    auto ldgA = [&](int kb) {
#pragma unroll
        for (int i = 0; i < 2; i++) {
            int slot = tid + i * 256;
            if constexpr (A_COL == 0) {
                int row = slot >> 2, v = slot & 3;  // 128 rows x 4 uint4
                ra[i] = *reinterpret_cast<const uint4*>(A + (size_t)(m0 + row) * lda + (size_t)kb * BK + v * 8);
            } else {
                int row = slot >> 4, v = slot & 15;  // 32 rows x 16 uint4
                ra[i] = *reinterpret_cast<const uint4*>(A + ((size_t)kb * BK + row) * (size_t)lda + m0 + v * 8);
            }
        }
    };
    auto stsA = [&](int buf) {
#pragma unroll
        for (int i = 0; i < 2; i++) {
            int slot = tid + i * 256;
            if constexpr (A_COL == 0) {
                int row = slot >> 2, v = slot & 3;
                *reinterpret_cast<uint4*>(&As[buf][row * LDAS + v * 8]) = ra[i];
            } else {
                int row = slot >> 4, v = slot & 15;
                *reinterpret_cast<uint4*>(&As[buf][row * LDAS + v * 8]) = ra[i];
            }
        }
    };
    auto ldgB = [&](int kb) {
#pragma unroll
        for (int i = 0; i < 2; i++) {
            int slot = tid + i * 256;
            if constexpr (B_NMAJ != 0) {
                int row = slot >> 2, v = slot & 3;  // 128 n-rows x 4 uint4
                rb[i] = *reinterpret_cast<const uint4*>(Bm + (size_t)(n0 + row) * ldb + (size_t)kb * BK + v * 8);
            } else {
                int row = slot >> 4, v = slot & 15; // 32 k-rows x 16 uint4
                rb[i] = *reinterpret_cast<const uint4*>(Bm + ((size_t)kb * BK + row) * (size_t)ldb + n0 + v * 8);
            }
        }
    };
    auto stsB = [&](int buf) {
#pragma unroll
        for (int i = 0; i < 2; i++) {
            int slot = tid + i * 256;
            if constexpr (B_NMAJ != 0) {
                int row = slot >> 2, v = slot & 3;
                *reinterpret_cast<uint4*>(&Bs[buf][row * LDBS + v * 8]) = rb[i];
            } else {
                int row = slot >> 4, v = slot & 15;
                *reinterpret_cast<uint4*>(&Bs[buf][row * LDBS + v * 8]) = rb[i];
            }
        }
    };

    using ALay = typename std::conditional<(A_COL != 0), wmma::col_major, wmma::row_major>::type;
    using BLay = typename std::conditional<(B_NMAJ != 0), wmma::col_major, wmma::row_major>::type;

    auto compute = [&](int buf) {
#pragma unroll
        for (int kk = 0; kk < 2; kk++) {
            wmma::fragment<wmma::matrix_a, 16, 16, 16, __nv_bfloat16, ALay> af[4];
            wmma::fragment<wmma::matrix_b, 16, 16, 16, __nv_bfloat16, BLay> bf[2];
#pragma unroll
            for (int i = 0; i < 4; i++) {
                const __nv_bfloat16* p;
                if constexpr (A_COL == 0) p = &As[buf][(wm * 64 + i * 16) * LDAS + kk * 16];
                else                      p = &As[buf][(kk * 16) * LDAS + wm * 64 + i * 16];
                wmma::load_matrix_sync(af[i], p, LDAS);
            }
#pragma unroll
            for (int j = 0; j < 2; j++) {
                const __nv_bfloat16* p;
                if constexpr (B_NMAJ != 0) p = &Bs[buf][(wn * 32 + j * 16) * LDBS + kk * 16];
                else                       p = &Bs[buf][(kk * 16) * LDBS + wn * 32 + j * 16];
                wmma::load_matrix_sync(bf[j], p, LDBS);
            }
#pragma unroll
            for (int i = 0; i < 4; i++)
#pragma unroll
                for (int j = 0; j < 2; j++)
                    wmma::mma_sync(acc[i][j], af[i], bf[j], acc[i][j]);
        }
    };

    ldgA(0); ldgB(0);
    stsA(0); stsB(0);
    __syncthreads();
    for (int kb = 0; kb < nk; kb++) {
        int buf = kb & 1;
        if (kb + 1 < nk) { ldgA(kb + 1); ldgB(kb + 1); }
        compute(buf);
        if (kb + 1 < nk) { stsA(buf ^ 1); stsB(buf ^ 1); }
        __syncthreads();
    }

    // ---- epilogue: stage each 16x16 fragment via smem (reuse As) ----
    float* stg = reinterpret_cast<float*>(&As[0][0]) + w * 256;
    const size_t cbase = (size_t)bz * sC;
#pragma unroll
    for (int i = 0; i < 4; i++) {
#pragma unroll
        for (int j = 0; j < 2; j++) {
            wmma::store_matrix_sync(stg, acc[i][j], 16, wmma::mem_row_major);
            __syncwarp();
            const int rbase = m0 + wm * 64 + i * 16;
            const int cb = n0 + wn * 32 + j * 16;
#pragma unroll
            for (int e = 0; e < 8; e++) {
                int idx = e * 32 + lane;
                int r = idx >> 4, c = idx & 15;
                float v = stg[idx] * scale;
                int gn = cb + c;
                if (bias) v += bias[gn];
                size_t off = cbase + (size_t)(rbase + r) * ldc + gn;
                if constexpr (MODE == 0) {
                    reinterpret_cast<__nv_bfloat16*>(Cout)[off] = __float2bfloat16(v);
                } else {
                    reinterpret_cast<float*>(Cout)[off] = v + res[off];
                }
            }
            __syncwarp();
        }
    }
}

// ---------------- host ----------------
static __nv_bfloat16* symbf(const void* s) {
    void* p = nullptr;
    cudaGetSymbolAddress(&p, s);
    return reinterpret_cast<__nv_bfloat16*>(p);
}

extern "C" void kernel_launch(void* const* d_in, const int* in_sizes, int n_in,
                              void* d_out, int out_size) {
    using namespace cfg;
    const float* x_l    = (const float*)d_in[0];
    const float* x_r    = (const float*)d_in[1];
    const float* lp1_w1 = (const float*)d_in[2];  const float* lp1_b1 = (const float*)d_in[3];
    const float* lp1_w2 = (const float*)d_in[4];  const float* lp1_b2 = (const float*)d_in[5];
    const float* rp1_w1 = (const float*)d_in[6];  const float* rp1_b1 = (const float*)d_in[7];
    const float* rp1_w2 = (const float*)d_in[8];  const float* rp1_b2 = (const float*)d_in[9];
    const float* lp2_w1 = (const float*)d_in[10]; const float* lp2_b1 = (const float*)d_in[11];
    const float* lp2_w2 = (const float*)d_in[12]; const float* lp2_b2 = (const float*)d_in[13];
    const float* rp2_w1 = (const float*)d_in[14]; const float* rp2_b1 = (const float*)d_in[15];
    const float* rp2_w2 = (const float*)d_in[16]; const float* rp2_b2 = (const float*)d_in[17];
    const float* lp3_w  = (const float*)d_in[18]; const float* lp3_b  = (const float*)d_in[19];
    const float* rp3_w  = (const float*)d_in[20]; const float* rp3_b  = (const float*)d_in[21];

    __nv_bfloat16* xl16 = symbf(g_xl16);
    __nv_bfloat16* xr16 = symbf(g_xr16);
    __nv_bfloat16* w16  = symbf(g_w16);
    __nv_bfloat16* h16  = symbf(g_h16);
    __nv_bfloat16* Ql   = symbf(g_Ql);
    __nv_bfloat16* Qr   = symbf(g_Qr);
    __nv_bfloat16* Vl   = symbf(g_Vl);
    __nv_bfloat16* Vr   = symbf(g_Vr);
    __nv_bfloat16* Sp   = symbf(g_S);
    __nv_bfloat16* P1   = symbf(g_P1);
    __nv_bfloat16* P2   = symbf(g_P2);
    __nv_bfloat16* F1   = symbf(g_F1);
    __nv_bfloat16* F2   = symbf(g_F2);

    const int n  = BT * C;
    const int nw = C * C;
    const float scale = 0.04419417382415922f;  // 512^-0.5

    // fp32 -> bf16 conversions
    k_f2bf<<<(n / 4 + 255) / 256, 256>>>(x_l, xl16, n / 4);
    k_f2bf<<<(n / 4 + 255) / 256, 256>>>(x_r, xr16, n / 4);
    k_f2bf<<<(nw / 4 + 255) / 256, 256>>>(lp1_w1, w16 + 0 * nw, nw / 4);
    k_f2bf<<<(nw / 4 + 255) / 256, 256>>>(rp1_w1, w16 + 1 * nw, nw / 4);
    k_f2bf<<<(nw / 4 + 255) / 256, 256>>>(lp2_w1, w16 + 2 * nw, nw / 4);
    k_f2bf<<<(nw / 4 + 255) / 256, 256>>>(rp2_w1, w16 + 3 * nw, nw / 4);
    k_f2bf<<<(nw / 4 + 255) / 256, 256>>>(lp3_w,  w16 + 4 * nw, nw / 4);
    k_f2bf<<<(nw / 4 + 255) / 256, 256>>>(rp3_w,  w16 + 5 * nw, nw / 4);

    dim3 gP(C / 128, BT / 128, 1);
    const int gEl = (n + 255) / 256;

    // projections: h = x @ w1^T + b1, then depthwise conv -> Q/V (bf16)
    k_gemm<0, 1, 0><<<gP, 256>>>(xl16, w16 + 0 * nw, h16, lp1_b1, nullptr,
                                 BT, C, C, C, C, C, 0LL, 0LL, 0LL, 1.f);
    k_dwconv<<<gEl, 256>>>(h16, lp1_w2, lp1_b2, Ql);

    k_gemm<0, 1, 0><<<gP, 256>>>(xr16, w16 + 1 * nw, h16, rp1_b1, nullptr,
                                 BT, C, C, C, C, C, 0LL, 0LL, 0LL, 1.f);
    k_dwconv<<<gEl, 256>>>(h16, rp1_w2, rp1_b2, Qr);

    k_gemm<0, 1, 0><<<gP, 256>>>(xl16, w16 + 2 * nw, h16, lp2_b1, nullptr,
                                 BT, C, C, C, C, C, 0LL, 0LL, 0LL, 1.f);
    k_dwconv<<<gEl, 256>>>(h16, lp2_w2, lp2_b2, Vl);

    k_gemm<0, 1, 0><<<gP, 256>>>(xr16, w16 + 3 * nw, h16, rp2_b1, nullptr,
                                 BT, C, C, C, C, C, 0LL, 0LL, 0LL, 1.f);
    k_dwconv<<<gEl, 256>>>(h16, rp2_w2, rp2_b2, Vr);

    // S[b,t,s] = scale * Q_l[b,t,:] . Q_r[b,s,:]
    dim3 gS(T / 128, T / 128, B);
    k_gemm<0, 1, 0><<<gS, 256>>>(Ql, Qr, Sp, nullptr, nullptr,
                                 T, T, C, C, C, T,
                                 (long long)T * C, (long long)T * C, (long long)T * T, scale);

    // softmaxes
    k_softmax_row<<<B * T, 256>>>(Sp, P1);
    k_softmax_col<<<dim3(T / 32, B), dim3(32, 8)>>>(Sp, P2);

    // F1[b,t,c] = sum_s P1[b,t,s] V_r[b,s,c]   (A row-major, B k-major)
    dim3 gF(C / 128, T / 128, B);
    k_gemm<0, 0, 0><<<gF, 256>>>(P1, Vr, F1, nullptr, nullptr,
                                 T, C, T, T, C, C,
                                 (long long)T * T, (long long)T * C, (long long)T * C, 1.f);
    // F2[b,s,c] = sum_t P2[b,t,s] V_l[b,t,c]   (A = P2 accessed transposed)
    k_gemm<1, 0, 0><<<gF, 256>>>(P2, Vl, F2, nullptr, nullptr,
                                 T, C, T, T, C, C,
                                 (long long)T * T, (long long)T * C, (long long)T * C, 1.f);

    // out_l = x_l + F1 @ lp3^T + lp3_b ; out_r = x_r + F2 @ rp3^T + rp3_b
    k_gemm<0, 1, 1><<<gP, 256>>>(F1, w16 + 4 * nw, d_out, lp3_b, x_l,
                                 BT, C, C, C, C, C, 0LL, 0LL, 0LL, 1.f);
    k_gemm<0, 1, 1><<<gP, 256>>>(F2, w16 + 5 * nw, (float*)d_out + (size_t)BT * C, rp3_b, x_r,
                                 BT, C, C, C, C, C, 0LL, 0LL, 0LL, 1.f);
}

// round 3
// speedup vs baseline: 1.2486x; 1.2486x over previous
#include <cuda_runtime.h>
#include <cuda_bf16.h>
#include <cstdint>

namespace cfg {
constexpr int B = 8, T = 2048, C = 512;
constexpr int BT = B * T;  // 16384
}

// ---------------- scratch (static device arrays; no allocation) ----------------
__device__ __nv_bfloat16 g_xl16[cfg::BT * cfg::C];
__device__ __nv_bfloat16 g_xr16[cfg::BT * cfg::C];
__device__ __nv_bfloat16 g_w16[6 * cfg::C * cfg::C];
__device__ __nv_bfloat16 g_h16[cfg::BT * cfg::C];
__device__ __nv_bfloat16 g_Ql [cfg::BT * cfg::C];
__device__ __nv_bfloat16 g_Qr [cfg::BT * cfg::C];
__device__ __nv_bfloat16 g_VlT[cfg::B * cfg::C * cfg::T];
__device__ __nv_bfloat16 g_VrT[cfg::B * cfg::C * cfg::T];
__device__ __nv_bfloat16 g_S  [(size_t)cfg::B * cfg::T * cfg::T];
__device__ __nv_bfloat16 g_S2 [(size_t)cfg::B * cfg::T * cfg::T];
__device__ __nv_bfloat16 g_P1 [(size_t)cfg::B * cfg::T * cfg::T];
__device__ __nv_bfloat16 g_P2 [(size_t)cfg::B * cfg::T * cfg::T];
__device__ __nv_bfloat16 g_F1 [cfg::BT * cfg::C];
__device__ __nv_bfloat16 g_F2 [cfg::BT * cfg::C];

// ---------------- helpers ----------------
__device__ __forceinline__ uint32_t smem_u32(const void* p) {
    uint32_t a;
    asm("{ .reg .u64 t; cvta.to.shared.u64 t, %1; cvt.u32.u64 %0, t; }" : "=r"(a) : "l"(p));
    return a;
}

#define CP_ASYNC16(dst, src) \
    asm volatile("cp.async.cg.shared.global [%0], [%1], 16;" :: "r"(dst), "l"(src) : "memory")
#define CP_COMMIT() asm volatile("cp.async.commit_group;" ::: "memory")
#define CP_WAIT(n)  asm volatile("cp.async.wait_group %0;" :: "n"(n) : "memory")

#define LDSM4(r, addr) \
    asm volatile("ldmatrix.sync.aligned.m8n8.x4.shared.b16 {%0,%1,%2,%3}, [%4];" \
        : "=r"((r)[0]), "=r"((r)[1]), "=r"((r)[2]), "=r"((r)[3]) : "r"(addr))

#define MMA16816(c, a, b0, b1) \
    asm volatile("mma.sync.aligned.m16n8k16.row.col.f32.bf16.bf16.f32 " \
        "{%0,%1,%2,%3}, {%4,%5,%6,%7}, {%8,%9}, {%0,%1,%2,%3};" \
        : "+f"((c)[0]), "+f"((c)[1]), "+f"((c)[2]), "+f"((c)[3]) \
        : "r"((a)[0]), "r"((a)[1]), "r"((a)[2]), "r"((a)[3]), "r"(b0), "r"(b1))

// ---------------- mma.sync bf16 GEMM ----------------
// D[m,n] = scale * sum_k A[m,k]*B[n,k]  (+bias[n]) (+res for MODE1, fp32 out)
// A row-major [M,K] lda ; B n-major [N,K] ldb.  BM=BN=128, BK=32, 4-stage cp.async.
template <int MODE>
__global__ __launch_bounds__(256, 2)
void k_gemm_mma(const __nv_bfloat16* __restrict__ A,
                const __nv_bfloat16* __restrict__ Bm,
                void* __restrict__ Cout,
                const float* __restrict__ bias,
                const float* __restrict__ res,
                int M, int N, int K, int lda, int ldb, int ldc,
                long long sA, long long sB, long long sC, float scale) {
    constexpr int NS = 4;
    constexpr int STAGE = 2 * 128 * 80;        // A(10240) + B(10240) bytes
    extern __shared__ __align__(16) char dyn_raw[];
    const uint32_t sbase = smem_u32(dyn_raw);

    const int tid = threadIdx.x;
    const int lane = tid & 31, w = tid >> 5;
    const int wm = w & 3, wn = w >> 2;         // 4 m-warps x 2 n-warps; warp tile 32x64
    const int m0 = blockIdx.y * 128;
    const int n0 = blockIdx.x * 128;
    A  += (size_t)blockIdx.z * sA;
    Bm += (size_t)blockIdx.z * sB;

    const int nk = K >> 5;

    auto issue = [&](int kc, int s) {
        const uint32_t aB = sbase + s * STAGE;
        const uint32_t bB = aB + 10240;
        const __nv_bfloat16* Ag = A + (size_t)kc * 32;
        const __nv_bfloat16* Bg = Bm + (size_t)kc * 32;
#pragma unroll
        for (int i = 0; i < 2; i++) {
            int slot = tid + i * 256;
            int row = slot >> 2, v = slot & 3;
            CP_ASYNC16(aB + row * 80 + v * 16, (const void*)(Ag + (size_t)(m0 + row) * lda + v * 8));
        }
#pragma unroll
        for (int i = 0; i < 2; i++) {
            int slot = tid + i * 256;
            int row = slot >> 2, v = slot & 3;
            CP_ASYNC16(bB + row * 80 + v * 16, (const void*)(Bg + (size_t)(n0 + row) * ldb + v * 8));
        }
    };

    // per-thread ldmatrix base offsets (bytes)
    const uint32_t a_off = (uint32_t)((wm * 32 + (lane & 15)) * 80 + ((lane >> 4) * 8) * 2);
    const uint32_t b_off = (uint32_t)((wn * 64 + (lane & 7) + ((lane >> 4) << 3)) * 80 +
                                      (((lane >> 3) & 1) * 8) * 2);

    float acc[2][8][4];
#pragma unroll
    for (int mi = 0; mi < 2; mi++)
#pragma unroll
        for (int nj = 0; nj < 8; nj++)
#pragma unroll
            for (int e = 0; e < 4; e++) acc[mi][nj][e] = 0.f;

    // prologue: stages 0..NS-2
#pragma unroll
    for (int p = 0; p < NS - 1; p++) { issue(p, p); CP_COMMIT(); }

    for (int kb = 0; kb < nk; kb++) {
        if (kb + NS - 1 < nk) issue(kb + NS - 1, (kb + NS - 1) & (NS - 1));
        CP_COMMIT();
        CP_WAIT(NS - 1);
        __syncthreads();

        const uint32_t aB = sbase + (kb & (NS - 1)) * STAGE;
        const uint32_t bB = aB + 10240;
#pragma unroll
        for (int ks = 0; ks < 2; ks++) {
            uint32_t af[2][4], bf[4][4];
#pragma unroll
            for (int mi = 0; mi < 2; mi++)
                LDSM4(af[mi], aB + a_off + mi * (16 * 80) + ks * 32);
#pragma unroll
            for (int nb = 0; nb < 4; nb++)
                LDSM4(bf[nb], bB + b_off + nb * (16 * 80) + ks * 32);
#pragma unroll
            for (int mi = 0; mi < 2; mi++)
#pragma unroll
                for (int nj = 0; nj < 8; nj++)
                    MMA16816(acc[mi][nj], af[mi], bf[nj >> 1][(nj & 1) * 2], bf[nj >> 1][(nj & 1) * 2 + 1]);
        }
        __syncthreads();
    }

    // epilogue: direct stores from fragment layout
    const size_t cb = (size_t)blockIdx.z * sC;
#pragma unroll
    for (int mi = 0; mi < 2; mi++) {
        const int r0 = m0 + wm * 32 + mi * 16 + (lane >> 2);
#pragma unroll
        for (int nj = 0; nj < 8; nj++) {
            const int c = n0 + wn * 64 + nj * 8 + (lane & 3) * 2;
            float v0 = acc[mi][nj][0] * scale, v1 = acc[mi][nj][1] * scale;
            float v2 = acc[mi][nj][2] * scale, v3 = acc[mi][nj][3] * scale;
            if constexpr (MODE == 0) {
                if (bias) {
                    float b0 = bias[c], b1 = bias[c + 1];
                    v0 += b0; v1 += b1; v2 += b0; v3 += b1;
                }
                __nv_bfloat16* O = (__nv_bfloat16*)Cout;
                *reinterpret_cast<__nv_bfloat162*>(&O[cb + (size_t)r0 * ldc + c]) =
                    __floats2bfloat162_rn(v0, v1);
                *reinterpret_cast<__nv_bfloat162*>(&O[cb + (size_t)(r0 + 8) * ldc + c]) =
                    __floats2bfloat162_rn(v2, v3);
            } else {
                float b0 = bias[c], b1 = bias[c + 1];
                float* O = (float*)Cout;
                size_t o1 = cb + (size_t)r0 * ldc + c;
                size_t o2 = cb + (size_t)(r0 + 8) * ldc + c;
                float2 r1 = *reinterpret_cast<const float2*>(&res[o1]);
                float2 r2 = *reinterpret_cast<const float2*>(&res[o2]);
                *reinterpret_cast<float2*>(&O[o1]) = make_float2(v0 + b0 + r1.x, v1 + b1 + r1.y);
                *reinterpret_cast<float2*>(&O[o2]) = make_float2(v2 + b0 + r2.x, v3 + b1 + r2.y);
            }
        }
    }
}

// ---------------- elementwise / conversion kernels ----------------
__global__ void k_f2bf(const float* __restrict__ in, __nv_bfloat16* __restrict__ out, int n4) {
    int i = blockIdx.x * blockDim.x + threadIdx.x;
    if (i < n4) {
        float4 f = reinterpret_cast<const float4*>(in)[i];
        __nv_bfloat162* o = reinterpret_cast<__nv_bfloat162*>(out);
        o[2 * i]     = __floats2bfloat162_rn(f.x, f.y);
        o[2 * i + 1] = __floats2bfloat162_rn(f.z, f.w);
    }
}

__global__ void k_f2bf6(const float* s0, const float* s1, const float* s2,
                        const float* s3, const float* s4, const float* s5,
                        __nv_bfloat16* __restrict__ out) {
    int i = blockIdx.x * blockDim.x + threadIdx.x;  // 6*65536
    int which = i >> 16, off = i & 65535;
    const float* s = which == 0 ? s0 : which == 1 ? s1 : which == 2 ? s2
                    : which == 3 ? s3 : which == 4 ? s4 : s5;
    float4 f = reinterpret_cast<const float4*>(s)[off];
    __nv_bfloat162* o = reinterpret_cast<__nv_bfloat162*>(out + ((size_t)which << 18));
    o[2 * off]     = __floats2bfloat162_rn(f.x, f.y);
    o[2 * off + 1] = __floats2bfloat162_rn(f.z, f.w);
}

// depthwise conv k=3 (row-major out), Q path
__global__ void k_dwconv(const __nv_bfloat16* __restrict__ h,
                         const float* __restrict__ w2, const float* __restrict__ b2,
                         __nv_bfloat16* __restrict__ out) {
    int i = blockIdx.x * blockDim.x + threadIdx.x;
    if (i >= cfg::BT * cfg::C) return;
    int c = i % cfg::C;
    int t = (i / cfg::C) % cfg::T;
    float v = __bfloat162float(h[i]) * w2[c * 3 + 1] + b2[c];
    if (t > 0)          v += __bfloat162float(h[i - cfg::C]) * w2[c * 3 + 0];
    if (t < cfg::T - 1) v += __bfloat162float(h[i + cfg::C]) * w2[c * 3 + 2];
    out[i] = __float2bfloat16(v);
}

// depthwise conv k=3 fused with transpose: h (B,T,C) -> outT (B,C,T)
__global__ void k_dwconv_t(const __nv_bfloat16* __restrict__ h,
                           const float* __restrict__ w2, const float* __restrict__ b2,
                           __nv_bfloat16* __restrict__ outT) {
    __shared__ float s[34][33];
    const int b = blockIdx.z, t0 = blockIdx.x * 32, c0 = blockIdx.y * 32;
    const __nv_bfloat16* hb = h + (size_t)b * cfg::T * cfg::C;
    for (int i = threadIdx.y; i < 34; i += 8) {
        int t = t0 + i - 1;
        float v = 0.f;
        if (t >= 0 && t < cfg::T)
            v = __bfloat162float(hb[(size_t)t * cfg::C + c0 + threadIdx.x]);
        s[i][threadIdx.x] = v;
    }
    __syncthreads();
    const int x = threadIdx.x;  // t within tile
    for (int j = threadIdx.y; j < 32; j += 8) {
        int c = c0 + j;
        float v = s[x][j] * w2[c * 3 + 0] + s[x + 1][j] * w2[c * 3 + 1]
                + s[x + 2][j] * w2[c * 3 + 2] + b2[c];
        outT[((size_t)b * cfg::C + c) * cfg::T + t0 + x] = __float2bfloat16(v);
    }
}

// bf16 matrix transpose per batch: S (B,T,T) -> S2[b,s,t] = S[b,t,s]
__global__ void k_trans(const __nv_bfloat16* __restrict__ S, __nv_bfloat16* __restrict__ S2) {
    __shared__ __nv_bfloat16 tile[32][34];
    const int b = blockIdx.z, t0 = blockIdx.y * 32, s0 = blockIdx.x * 32;
    const __nv_bfloat16* Sb = S + (size_t)b * cfg::T * cfg::T;
    __nv_bfloat16* S2b = S2 + (size_t)b * cfg::T * cfg::T;
    for (int i = threadIdx.y; i < 32; i += 8)
        tile[i][threadIdx.x] = Sb[(size_t)(t0 + i) * cfg::T + s0 + threadIdx.x];
    __syncthreads();
    for (int i = threadIdx.y; i < 32; i += 8)
        S2b[(size_t)(s0 + i) * cfg::T + t0 + threadIdx.x] = tile[threadIdx.x][i];
}

// row softmax: one block per row of length T
__global__ void k_softmax_row(const __nv_bfloat16* __restrict__ S, __nv_bfloat16* __restrict__ P) {
    const size_t row = blockIdx.x;
    const __nv_bfloat16* s = S + row * cfg::T;
    __nv_bfloat16* p = P + row * cfg::T;
    const int tid = threadIdx.x;
    float v[8];
    float m = -1e30f;
#pragma unroll
    for (int j = 0; j < 8; j++) { v[j] = __bfloat162float(s[tid + j * 256]); m = fmaxf(m, v[j]); }
    __shared__ float red[256];
    red[tid] = m; __syncthreads();
    for (int o = 128; o > 0; o >>= 1) { if (tid < o) red[tid] = fmaxf(red[tid], red[tid + o]); __syncthreads(); }
    m = red[0]; __syncthreads();
    float sum = 0.f;
#pragma unroll
    for (int j = 0; j < 8; j++) { v[j] = __expf(v[j] - m); sum += v[j]; }
    red[tid] = sum; __syncthreads();
    for (int o = 128; o > 0; o >>= 1) { if (tid < o) red[tid] += red[tid + o]; __syncthreads(); }
    float inv = 1.f / red[0];
#pragma unroll
    for (int j = 0; j < 8; j++) p[tid + j * 256] = __float2bfloat16(v[j] * inv);
}

// ---------------- host ----------------
static __nv_bfloat16* symbf(const void* s) {
    void* p = nullptr;
    cudaGetSymbolAddress(&p, s);
    return reinterpret_cast<__nv_bfloat16*>(p);
}

extern "C" void kernel_launch(void* const* d_in, const int* in_sizes, int n_in,
                              void* d_out, int out_size) {
    using namespace cfg;
    const float* x_l    = (const float*)d_in[0];
    const float* x_r    = (const float*)d_in[1];
    const float* lp1_w1 = (const float*)d_in[2];  const float* lp1_b1 = (const float*)d_in[3];
    const float* lp1_w2 = (const float*)d_in[4];  const float* lp1_b2 = (const float*)d_in[5];
    const float* rp1_w1 = (const float*)d_in[6];  const float* rp1_b1 = (const float*)d_in[7];
    const float* rp1_w2 = (const float*)d_in[8];  const float* rp1_b2 = (const float*)d_in[9];
    const float* lp2_w1 = (const float*)d_in[10]; const float* lp2_b1 = (const float*)d_in[11];
    const float* lp2_w2 = (const float*)d_in[12]; const float* lp2_b2 = (const float*)d_in[13];
    const float* rp2_w1 = (const float*)d_in[14]; const float* rp2_b1 = (const float*)d_in[15];
    const float* rp2_w2 = (const float*)d_in[16]; const float* rp2_b2 = (const float*)d_in[17];
    const float* lp3_w  = (const float*)d_in[18]; const float* lp3_b  = (const float*)d_in[19];
    const float* rp3_w  = (const float*)d_in[20]; const float* rp3_b  = (const float*)d_in[21];

    __nv_bfloat16* xl16 = symbf(g_xl16);
    __nv_bfloat16* xr16 = symbf(g_xr16);
    __nv_bfloat16* w16  = symbf(g_w16);
    __nv_bfloat16* h16  = symbf(g_h16);
    __nv_bfloat16* Ql   = symbf(g_Ql);
    __nv_bfloat16* Qr   = symbf(g_Qr);
    __nv_bfloat16* VlT  = symbf(g_VlT);
    __nv_bfloat16* VrT  = symbf(g_VrT);
    __nv_bfloat16* Sp   = symbf(g_S);
    __nv_bfloat16* S2   = symbf(g_S2);
    __nv_bfloat16* P1   = symbf(g_P1);
    __nv_bfloat16* P2   = symbf(g_P2);
    __nv_bfloat16* F1   = symbf(g_F1);
    __nv_bfloat16* F2   = symbf(g_F2);

    const int n  = BT * C;
    const int nw = C * C;
    const float scale = 0.04419417382415922f;  // 512^-0.5
    const int DSM = 4 * 2 * 128 * 80;          // 81920 B

    cudaFuncSetAttribute(k_gemm_mma<0>, cudaFuncAttributeMaxDynamicSharedMemorySize, DSM);
    cudaFuncSetAttribute(k_gemm_mma<1>, cudaFuncAttributeMaxDynamicSharedMemorySize, DSM);

    // conversions
    k_f2bf<<<(n / 4 + 255) / 256, 256>>>(x_l, xl16, n / 4);
    k_f2bf<<<(n / 4 + 255) / 256, 256>>>(x_r, xr16, n / 4);
    k_f2bf6<<<(6 * (nw / 4)) / 256, 256>>>(lp1_w1, rp1_w1, lp2_w1, rp2_w1, lp3_w, rp3_w, w16);

    dim3 gP(C / 128, BT / 128, 1);
    const int gEl = (n + 255) / 256;
    dim3 gT(T / 32, C / 32, B);

    // projections: h = x @ w1^T + b1; dwconv -> Q (row-major) / V^T (B,C,T)
    k_gemm_mma<0><<<gP, 256, DSM>>>(xl16, w16 + 0 * nw, h16, lp1_b1, nullptr,
                                    BT, C, C, C, C, C, 0LL, 0LL, 0LL, 1.f);
    k_dwconv<<<gEl, 256>>>(h16, lp1_w2, lp1_b2, Ql);

    k_gemm_mma<0><<<gP, 256, DSM>>>(xr16, w16 + 1 * nw, h16, rp1_b1, nullptr,
                                    BT, C, C, C, C, C, 0LL, 0LL, 0LL, 1.f);
    k_dwconv<<<gEl, 256>>>(h16, rp1_w2, rp1_b2, Qr);

    k_gemm_mma<0><<<gP, 256, DSM>>>(xl16, w16 + 2 * nw, h16, lp2_b1, nullptr,
                                    BT, C, C, C, C, C, 0LL, 0LL, 0LL, 1.f);
    k_dwconv_t<<<gT, dim3(32, 8)>>>(h16, lp2_w2, lp2_b2, VlT);

    k_gemm_mma<0><<<gP, 256, DSM>>>(xr16, w16 + 3 * nw, h16, rp2_b1, nullptr,
                                    BT, C, C, C, C, C, 0LL, 0LL, 0LL, 1.f);
    k_dwconv_t<<<gT, dim3(32, 8)>>>(h16, rp2_w2, rp2_b2, VrT);

    // S[b,t,s] = scale * Ql.Qr ; S2 = S^T via transpose
    dim3 gS(T / 128, T / 128, B);
    k_gemm_mma<0><<<gS, 256, DSM>>>(Ql, Qr, Sp, nullptr, nullptr,
                                    T, T, C, C, C, T,
                                    (long long)T * C, (long long)T * C, (long long)T * T, scale);
    k_trans<<<dim3(T / 32, T / 32, B), dim3(32, 8)>>>(Sp, S2);

    // row softmaxes (both coalesced)
    k_softmax_row<<<B * T, 256>>>(Sp, P1);
    k_softmax_row<<<B * T, 256>>>(S2, P2);

    // F1[b,t,c] = sum_s P1[t,s] VrT[c,s] ; F2[b,s,c] = sum_t P2[s,t] VlT[c,t]
    dim3 gF(C / 128, T / 128, B);
    k_gemm_mma<0><<<gF, 256, DSM>>>(P1, VrT, F1, nullptr, nullptr,
                                    T, C, T, T, T, C,
                                    (long long)T * T, (long long)C * T, (long long)T * C, 1.f);
    k_gemm_mma<0><<<gF, 256, DSM>>>(P2, VlT, F2, nullptr, nullptr,
                                    T, C, T, T, T, C,
                                    (long long)T * T, (long long)C * T, (long long)T * C, 1.f);

    // out = x + F @ w3^T + b3  (fp32 + residual)
    k_gemm_mma<1><<<gP, 256, DSM>>>(F1, w16 + 4 * nw, d_out, lp3_b, x_l,
                                    BT, C, C, C, C, C, 0LL, 0LL, 0LL, 1.f);
    k_gemm_mma<1><<<gP, 256, DSM>>>(F2, w16 + 5 * nw, (float*)d_out + (size_t)BT * C, rp3_b, x_r,
                                    BT, C, C, C, C, C, 0LL, 0LL, 0LL, 1.f);
}

// round 4
// speedup vs baseline: 1.5052x; 1.2055x over previous
#include <cuda_runtime.h>
#include <cuda_bf16.h>
#include <cstdint>

namespace cfg {
constexpr int B = 8, T = 2048, C = 512;
constexpr int BT = B * T;  // 16384
}

// ---------------- scratch (static device arrays; no allocation) ----------------
__device__ __nv_bfloat16 g_xl16[cfg::BT * cfg::C];
__device__ __nv_bfloat16 g_xr16[cfg::BT * cfg::C];
__device__ __nv_bfloat16 g_w16[6 * cfg::C * cfg::C];
__device__ __nv_bfloat16 g_h16[cfg::BT * cfg::C];
__device__ __nv_bfloat16 g_Ql [cfg::BT * cfg::C];
__device__ __nv_bfloat16 g_Qr [cfg::BT * cfg::C];
__device__ __nv_bfloat16 g_VlT[cfg::B * cfg::C * cfg::T];
__device__ __nv_bfloat16 g_VrT[cfg::B * cfg::C * cfg::T];
__device__ __nv_bfloat16 g_S  [(size_t)cfg::B * cfg::T * cfg::T];
__device__ __nv_bfloat16 g_S2 [(size_t)cfg::B * cfg::T * cfg::T];
__device__ __nv_bfloat16 g_P1 [(size_t)cfg::B * cfg::T * cfg::T];
__device__ __nv_bfloat16 g_P2 [(size_t)cfg::B * cfg::T * cfg::T];
__device__ __nv_bfloat16 g_F1 [cfg::BT * cfg::C];
__device__ __nv_bfloat16 g_F2 [cfg::BT * cfg::C];

// ---------------- helpers ----------------
__device__ __forceinline__ uint32_t smem_u32(const void* p) {
    uint32_t a;
    asm("{ .reg .u64 t; cvta.to.shared.u64 t, %1; cvt.u32.u64 %0, t; }" : "=r"(a) : "l"(p));
    return a;
}

#define CP_ASYNC16(dst, src) \
    asm volatile("cp.async.cg.shared.global [%0], [%1], 16;" :: "r"(dst), "l"(src) : "memory")
#define CP_COMMIT() asm volatile("cp.async.commit_group;" ::: "memory")
#define CP_WAIT(n)  asm volatile("cp.async.wait_group %0;" :: "n"(n) : "memory")

#define LDSM4(r, addr) \
    asm volatile("ldmatrix.sync.aligned.m8n8.x4.shared.b16 {%0,%1,%2,%3}, [%4];" \
        : "=r"((r)[0]), "=r"((r)[1]), "=r"((r)[2]), "=r"((r)[3]) : "r"(addr))

#define MMA16816(c, a, b0, b1) \
    asm volatile("mma.sync.aligned.m16n8k16.row.col.f32.bf16.bf16.f32 " \
        "{%0,%1,%2,%3}, {%4,%5,%6,%7}, {%8,%9}, {%0,%1,%2,%3};" \
        : "+f"((c)[0]), "+f"((c)[1]), "+f"((c)[2]), "+f"((c)[3]) \
        : "r"((a)[0]), "r"((a)[1]), "r"((a)[2]), "r"((a)[3]), "r"(b0), "r"(b1))

// SW128 swizzle of a byte offset whose row stride is 128B
#define SW128(o) ((o) ^ (((o) >> 3) & 0x70))

// ---------------- mma.sync bf16 GEMM (multistage, single-barrier) ----------------
// D[m,n] = scale * sum_k A[m,k]*B[n,k]  (+bias[n]) (+res for MODE1, fp32 out)
// A row-major [M,K] lda ; B n-major [N,K] ldb.  BM=BN=128, BK=64, NS=3 cp.async ring.
template <int MODE>
__global__ __launch_bounds__(256, 2)
void k_gemm_mma(const __nv_bfloat16* __restrict__ A,
                const __nv_bfloat16* __restrict__ Bm,
                void* __restrict__ Cout,
                const float* __restrict__ bias,
                const float* __restrict__ res,
                int M, int N, int K, int lda, int ldb, int ldc,
                long long sA, long long sB, long long sC, float scale) {
    constexpr int NS = 3;
    constexpr int STAGE = 2 * 128 * 128;       // A(16KB) + B(16KB)
    extern __shared__ __align__(16) char dyn_raw[];
    const uint32_t sbase = smem_u32(dyn_raw);

    const int tid = threadIdx.x;
    const int lane = tid & 31, w = tid >> 5;
    const int wm = w & 3, wn = w >> 2;         // 4 m-warps x 2 n-warps; warp tile 32x64
    const int m0 = blockIdx.y * 128;
    const int n0 = blockIdx.x * 128;
    A  += (size_t)blockIdx.z * sA;
    Bm += (size_t)blockIdx.z * sB;

    const int nk = K >> 6;

    auto issue = [&](int kc, int s) {
        const uint32_t aB = sbase + s * STAGE;
        const uint32_t bB = aB + 16384;
        const __nv_bfloat16* Ag = A + (size_t)kc * 64;
        const __nv_bfloat16* Bg = Bm + (size_t)kc * 64;
#pragma unroll
        for (int i = 0; i < 4; i++) {
            int slot = tid + i * 256;
            int row = slot >> 3, v = slot & 7;          // 128 rows x 8 x 16B
            CP_ASYNC16(aB + SW128(row * 128 + v * 16),
                       (const void*)(Ag + (size_t)(m0 + row) * lda + v * 8));
        }
#pragma unroll
        for (int i = 0; i < 4; i++) {
            int slot = tid + i * 256;
            int row = slot >> 3, v = slot & 7;
            CP_ASYNC16(bB + SW128(row * 128 + v * 16),
                       (const void*)(Bg + (size_t)(n0 + row) * ldb + v * 8));
        }
    };

    // per-thread ldmatrix geometry (swizzle XOR reduces to (lane&7)<<4)
    const uint32_t sxor = (uint32_t)(lane & 7) << 4;
    const uint32_t a_row = wm * 32 + (lane & 15);
    const uint32_t a_bc0 = (uint32_t)(lane >> 4) * 16;
    const uint32_t b_row = wn * 64 + (lane & 7) + ((lane >> 4) << 3);
    const uint32_t b_bc0 = (uint32_t)((lane >> 3) & 1) * 16;

    float acc[2][8][4];
#pragma unroll
    for (int mi = 0; mi < 2; mi++)
#pragma unroll
        for (int nj = 0; nj < 8; nj++)
#pragma unroll
            for (int e = 0; e < 4; e++) acc[mi][nj][e] = 0.f;

    // prologue: stages 0..NS-2 in flight
#pragma unroll
    for (int p = 0; p < NS - 1; p++) { issue(p, p); CP_COMMIT(); }
    CP_WAIT(NS - 2);
    __syncthreads();

    for (int kb = 0; kb < nk; kb++) {
        // refill the slot freed by iteration kb-1 (barrier at its end protects it)
        if (kb + NS - 1 < nk) issue(kb + NS - 1, (kb + NS - 1) % NS);
        CP_COMMIT();

        const uint32_t aB = sbase + (kb % NS) * STAGE;
        const uint32_t bB = aB + 16384;
#pragma unroll
        for (int ks = 0; ks < 4; ks++) {
            uint32_t af[2][4], bf[4][4];
            const uint32_t abc = ((uint32_t)ks * 32 + a_bc0) ^ sxor;
            const uint32_t bbc = ((uint32_t)ks * 32 + b_bc0) ^ sxor;
#pragma unroll
            for (int mi = 0; mi < 2; mi++)
                LDSM4(af[mi], aB + (a_row + mi * 16) * 128 + abc);
#pragma unroll
            for (int nb = 0; nb < 4; nb++)
                LDSM4(bf[nb], bB + (b_row + nb * 16) * 128 + bbc);
#pragma unroll
            for (int mi = 0; mi < 2; mi++)
#pragma unroll
                for (int nj = 0; nj < 8; nj++)
                    MMA16816(acc[mi][nj], af[mi], bf[nj >> 1][(nj & 1) * 2], bf[nj >> 1][(nj & 1) * 2 + 1]);
        }
        CP_WAIT(NS - 2);
        __syncthreads();
    }

    // epilogue: direct stores from fragment layout
    const size_t cb = (size_t)blockIdx.z * sC;
#pragma unroll
    for (int mi = 0; mi < 2; mi++) {
        const int r0 = m0 + wm * 32 + mi * 16 + (lane >> 2);
#pragma unroll
        for (int nj = 0; nj < 8; nj++) {
            const int c = n0 + wn * 64 + nj * 8 + (lane & 3) * 2;
            float v0 = acc[mi][nj][0] * scale, v1 = acc[mi][nj][1] * scale;
            float v2 = acc[mi][nj][2] * scale, v3 = acc[mi][nj][3] * scale;
            if constexpr (MODE == 0) {
                if (bias) {
                    float b0 = bias[c], b1 = bias[c + 1];
                    v0 += b0; v1 += b1; v2 += b0; v3 += b1;
                }
                __nv_bfloat16* O = (__nv_bfloat16*)Cout;
                *reinterpret_cast<__nv_bfloat162*>(&O[cb + (size_t)r0 * ldc + c]) =
                    __floats2bfloat162_rn(v0, v1);
                *reinterpret_cast<__nv_bfloat162*>(&O[cb + (size_t)(r0 + 8) * ldc + c]) =
                    __floats2bfloat162_rn(v2, v3);
            } else {
                float b0 = bias[c], b1 = bias[c + 1];
                float* O = (float*)Cout;
                size_t o1 = cb + (size_t)r0 * ldc + c;
                size_t o2 = cb + (size_t)(r0 + 8) * ldc + c;
                float2 r1 = *reinterpret_cast<const float2*>(&res[o1]);
                float2 r2 = *reinterpret_cast<const float2*>(&res[o2]);
                *reinterpret_cast<float2*>(&O[o1]) = make_float2(v0 + b0 + r1.x, v1 + b1 + r1.y);
                *reinterpret_cast<float2*>(&O[o2]) = make_float2(v2 + b0 + r2.x, v3 + b1 + r2.y);
            }
        }
    }
}

// ---------------- elementwise / conversion kernels ----------------
__global__ void k_f2bf(const float* __restrict__ in, __nv_bfloat16* __restrict__ out, int n4) {
    int i = blockIdx.x * blockDim.x + threadIdx.x;
    if (i < n4) {
        float4 f = reinterpret_cast<const float4*>(in)[i];
        __nv_bfloat162* o = reinterpret_cast<__nv_bfloat162*>(out);
        o[2 * i]     = __floats2bfloat162_rn(f.x, f.y);
        o[2 * i + 1] = __floats2bfloat162_rn(f.z, f.w);
    }
}

__global__ void k_f2bf6(const float* s0, const float* s1, const float* s2,
                        const float* s3, const float* s4, const float* s5,
                        __nv_bfloat16* __restrict__ out) {
    int i = blockIdx.x * blockDim.x + threadIdx.x;  // 6*65536
    int which = i >> 16, off = i & 65535;
    const float* s = which == 0 ? s0 : which == 1 ? s1 : which == 2 ? s2
                    : which == 3 ? s3 : which == 4 ? s4 : s5;
    float4 f = reinterpret_cast<const float4*>(s)[off];
    __nv_bfloat162* o = reinterpret_cast<__nv_bfloat162*>(out + ((size_t)which << 18));
    o[2 * off]     = __floats2bfloat162_rn(f.x, f.y);
    o[2 * off + 1] = __floats2bfloat162_rn(f.z, f.w);
}

// depthwise conv k=3 (row-major out), Q path
__global__ void k_dwconv(const __nv_bfloat16* __restrict__ h,
                         const float* __restrict__ w2, const float* __restrict__ b2,
                         __nv_bfloat16* __restrict__ out) {
    int i = blockIdx.x * blockDim.x + threadIdx.x;
    if (i >= cfg::BT * cfg::C) return;
    int c = i % cfg::C;
    int t = (i / cfg::C) % cfg::T;
    float v = __bfloat162float(h[i]) * w2[c * 3 + 1] + b2[c];
    if (t > 0)          v += __bfloat162float(h[i - cfg::C]) * w2[c * 3 + 0];
    if (t < cfg::T - 1) v += __bfloat162float(h[i + cfg::C]) * w2[c * 3 + 2];
    out[i] = __float2bfloat16(v);
}

// depthwise conv k=3 fused with transpose: h (B,T,C) -> outT (B,C,T)
__global__ void k_dwconv_t(const __nv_bfloat16* __restrict__ h,
                           const float* __restrict__ w2, const float* __restrict__ b2,
                           __nv_bfloat16* __restrict__ outT) {
    __shared__ float s[34][33];
    const int b = blockIdx.z, t0 = blockIdx.x * 32, c0 = blockIdx.y * 32;
    const __nv_bfloat16* hb = h + (size_t)b * cfg::T * cfg::C;
    for (int i = threadIdx.y; i < 34; i += 8) {
        int t = t0 + i - 1;
        float v = 0.f;
        if (t >= 0 && t < cfg::T)
            v = __bfloat162float(hb[(size_t)t * cfg::C + c0 + threadIdx.x]);
        s[i][threadIdx.x] = v;
    }
    __syncthreads();
    const int x = threadIdx.x;  // t within tile
    for (int j = threadIdx.y; j < 32; j += 8) {
        int c = c0 + j;
        float v = s[x][j] * w2[c * 3 + 0] + s[x + 1][j] * w2[c * 3 + 1]
                + s[x + 2][j] * w2[c * 3 + 2] + b2[c];
        outT[((size_t)b * cfg::C + c) * cfg::T + t0 + x] = __float2bfloat16(v);
    }
}

// bf16 matrix transpose per batch: S (B,T,T) -> S2[b,s,t] = S[b,t,s]
__global__ void k_trans(const __nv_bfloat16* __restrict__ S, __nv_bfloat16* __restrict__ S2) {
    __shared__ __nv_bfloat16 tile[32][34];
    const int b = blockIdx.z, t0 = blockIdx.y * 32, s0 = blockIdx.x * 32;
    const __nv_bfloat16* Sb = S + (size_t)b * cfg::T * cfg::T;
    __nv_bfloat16* S2b = S2 + (size_t)b * cfg::T * cfg::T;
    for (int i = threadIdx.y; i < 32; i += 8)
        tile[i][threadIdx.x] = Sb[(size_t)(t0 + i) * cfg::T + s0 + threadIdx.x];
    __syncthreads();
    for (int i = threadIdx.y; i < 32; i += 8)
        S2b[(size_t)(s0 + i) * cfg::T + t0 + threadIdx.x] = tile[threadIdx.x][i];
}

// row softmax: one block per row of length T
__global__ void k_softmax_row(const __nv_bfloat16* __restrict__ S, __nv_bfloat16* __restrict__ P) {
    const size_t row = blockIdx.x;
    const __nv_bfloat16* s = S + row * cfg::T;
    __nv_bfloat16* p = P + row * cfg::T;
    const int tid = threadIdx.x;
    float v[8];
    float m = -1e30f;
#pragma unroll
    for (int j = 0; j < 8; j++) { v[j] = __bfloat162float(s[tid + j * 256]); m = fmaxf(m, v[j]); }
    __shared__ float red[256];
    red[tid] = m; __syncthreads();
    for (int o = 128; o > 0; o >>= 1) { if (tid < o) red[tid] = fmaxf(red[tid], red[tid + o]); __syncthreads(); }
    m = red[0]; __syncthreads();
    float sum = 0.f;
#pragma unroll
    for (int j = 0; j < 8; j++) { v[j] = __expf(v[j] - m); sum += v[j]; }
    red[tid] = sum; __syncthreads();
    for (int o = 128; o > 0; o >>= 1) { if (tid < o) red[tid] += red[tid + o]; __syncthreads(); }
    float inv = 1.f / red[0];
#pragma unroll
    for (int j = 0; j < 8; j++) p[tid + j * 256] = __float2bfloat16(v[j] * inv);
}

// ---------------- host ----------------
static __nv_bfloat16* symbf(const void* s) {
    void* p = nullptr;
    cudaGetSymbolAddress(&p, s);
    return reinterpret_cast<__nv_bfloat16*>(p);
}

extern "C" void kernel_launch(void* const* d_in, const int* in_sizes, int n_in,
                              void* d_out, int out_size) {
    using namespace cfg;
    const float* x_l    = (const float*)d_in[0];
    const float* x_r    = (const float*)d_in[1];
    const float* lp1_w1 = (const float*)d_in[2];  const float* lp1_b1 = (const float*)d_in[3];
    const float* lp1_w2 = (const float*)d_in[4];  const float* lp1_b2 = (const float*)d_in[5];
    const float* rp1_w1 = (const float*)d_in[6];  const float* rp1_b1 = (const float*)d_in[7];
    const float* rp1_w2 = (const float*)d_in[8];  const float* rp1_b2 = (const float*)d_in[9];
    const float* lp2_w1 = (const float*)d_in[10]; const float* lp2_b1 = (const float*)d_in[11];
    const float* lp2_w2 = (const float*)d_in[12]; const float* lp2_b2 = (const float*)d_in[13];
    const float* rp2_w1 = (const float*)d_in[14]; const float* rp2_b1 = (const float*)d_in[15];
    const float* rp2_w2 = (const float*)d_in[16]; const float* rp2_b2 = (const float*)d_in[17];
    const float* lp3_w  = (const float*)d_in[18]; const float* lp3_b  = (const float*)d_in[19];
    const float* rp3_w  = (const float*)d_in[20]; const float* rp3_b  = (const float*)d_in[21];

    __nv_bfloat16* xl16 = symbf(g_xl16);
    __nv_bfloat16* xr16 = symbf(g_xr16);
    __nv_bfloat16* w16  = symbf(g_w16);
    __nv_bfloat16* h16  = symbf(g_h16);
    __nv_bfloat16* Ql   = symbf(g_Ql);
    __nv_bfloat16* Qr   = symbf(g_Qr);
    __nv_bfloat16* VlT  = symbf(g_VlT);
    __nv_bfloat16* VrT  = symbf(g_VrT);
    __nv_bfloat16* Sp   = symbf(g_S);
    __nv_bfloat16* S2   = symbf(g_S2);
    __nv_bfloat16* P1   = symbf(g_P1);
    __nv_bfloat16* P2   = symbf(g_P2);
    __nv_bfloat16* F1   = symbf(g_F1);
    __nv_bfloat16* F2   = symbf(g_F2);

    const int n  = BT * C;
    const int nw = C * C;
    const float scale = 0.04419417382415922f;  // 512^-0.5
    const int DSM = 3 * 2 * 128 * 128;         // 98304 B

    cudaFuncSetAttribute(k_gemm_mma<0>, cudaFuncAttributeMaxDynamicSharedMemorySize, DSM);
    cudaFuncSetAttribute(k_gemm_mma<1>, cudaFuncAttributeMaxDynamicSharedMemorySize, DSM);

    // conversions
    k_f2bf<<<(n / 4 + 255) / 256, 256>>>(x_l, xl16, n / 4);
    k_f2bf<<<(n / 4 + 255) / 256, 256>>>(x_r, xr16, n / 4);
    k_f2bf6<<<(6 * (nw / 4)) / 256, 256>>>(lp1_w1, rp1_w1, lp2_w1, rp2_w1, lp3_w, rp3_w, w16);

    dim3 gP(C / 128, BT / 128, 1);
    const int gEl = (n + 255) / 256;
    dim3 gT(T / 32, C / 32, B);

    // projections: h = x @ w1^T + b1; dwconv -> Q (row-major) / V^T (B,C,T)
    k_gemm_mma<0><<<gP, 256, DSM>>>(xl16, w16 + 0 * nw, h16, lp1_b1, nullptr,
                                    BT, C, C, C, C, C, 0LL, 0LL, 0LL, 1.f);
    k_dwconv<<<gEl, 256>>>(h16, lp1_w2, lp1_b2, Ql);

    k_gemm_mma<0><<<gP, 256, DSM>>>(xr16, w16 + 1 * nw, h16, rp1_b1, nullptr,
                                    BT, C, C, C, C, C, 0LL, 0LL, 0LL, 1.f);
    k_dwconv<<<gEl, 256>>>(h16, rp1_w2, rp1_b2, Qr);

    k_gemm_mma<0><<<gP, 256, DSM>>>(xl16, w16 + 2 * nw, h16, lp2_b1, nullptr,
                                    BT, C, C, C, C, C, 0LL, 0LL, 0LL, 1.f);
    k_dwconv_t<<<gT, dim3(32, 8)>>>(h16, lp2_w2, lp2_b2, VlT);

    k_gemm_mma<0><<<gP, 256, DSM>>>(xr16, w16 + 3 * nw, h16, rp2_b1, nullptr,
                                    BT, C, C, C, C, C, 0LL, 0LL, 0LL, 1.f);
    k_dwconv_t<<<gT, dim3(32, 8)>>>(h16, rp2_w2, rp2_b2, VrT);

    // S[b,t,s] = scale * Ql.Qr ; S2 = S^T via transpose
    dim3 gS(T / 128, T / 128, B);
    k_gemm_mma<0><<<gS, 256, DSM>>>(Ql, Qr, Sp, nullptr, nullptr,
                                    T, T, C, C, C, T,
                                    (long long)T * C, (long long)T * C, (long long)T * T, scale);
    k_trans<<<dim3(T / 32, T / 32, B), dim3(32, 8)>>>(Sp, S2);

    // row softmaxes (both coalesced)
    k_softmax_row<<<B * T, 256>>>(Sp, P1);
    k_softmax_row<<<B * T, 256>>>(S2, P2);

    // F1[b,t,c] = sum_s P1[t,s] VrT[c,s] ; F2[b,s,c] = sum_t P2[s,t] VlT[c,t]
    dim3 gF(C / 128, T / 128, B);
    k_gemm_mma<0><<<gF, 256, DSM>>>(P1, VrT, F1, nullptr, nullptr,
                                    T, C, T, T, T, C,
                                    (long long)T * T, (long long)C * T, (long long)T * C, 1.f);
    k_gemm_mma<0><<<gF, 256, DSM>>>(P2, VlT, F2, nullptr, nullptr,
                                    T, C, T, T, T, C,
                                    (long long)T * T, (long long)C * T, (long long)T * C, 1.f);

    // out = x + F @ w3^T + b3  (fp32 + residual)
    k_gemm_mma<1><<<gP, 256, DSM>>>(F1, w16 + 4 * nw, d_out, lp3_b, x_l,
                                    BT, C, C, C, C, C, 0LL, 0LL, 0LL, 1.f);
    k_gemm_mma<1><<<gP, 256, DSM>>>(F2, w16 + 5 * nw, (float*)d_out + (size_t)BT * C, rp3_b, x_r,
                                    BT, C, C, C, C, C, 0LL, 0LL, 0LL, 1.f);
}